// round 13
// baseline (speedup 1.0000x reference)
#include <cuda_runtime.h>
#include <cuda_fp16.h>
#include <cstdint>

#define NXX 64
#define DTT 1e-4f

__device__ __forceinline__ uint64_t pack2(float lo, float hi) {
    uint64_t r;
    asm("mov.b64 %0, {%1, %2};" : "=l"(r) : "f"(lo), "f"(hi));
    return r;
}
__device__ __forceinline__ void unpack2(uint64_t v, float& lo, float& hi) {
    asm("mov.b64 {%0, %1}, %2;" : "=f"(lo), "=f"(hi) : "l"(v));
}
__device__ __forceinline__ uint64_t fma2(uint64_t a, uint64_t b, uint64_t c) {
    uint64_t d;
    asm("fma.rn.f32x2 %0, %1, %2, %3;" : "=l"(d) : "l"(a), "l"(b), "l"(c));
    return d;
}
// pack two f32 into half2: h0 = lo, h1 = hi (first PTX source -> h1)
__device__ __forceinline__ uint32_t cvt_h2(float lo, float hi) {
    uint32_t d;
    asm("cvt.rn.f16x2.f32 %0, %1, %2;" : "=r"(d) : "f"(hi), "f"(lo));
    return d;
}
// packed half tanh: one MUFU instruction for TWO tanh
__device__ __forceinline__ uint32_t tanh_h2(uint32_t x) {
    uint32_t t;
    asm("tanh.approx.f16x2 %0, %1;" : "=r"(t) : "r"(x));
    return t;
}
__device__ __forceinline__ uint32_t hfma2_u(uint32_t a, uint32_t b, uint32_t c) {
    uint32_t d;
    asm("fma.rn.f16x2 %0, %1, %2, %3;" : "=r"(d) : "r"(a), "r"(b), "r"(c));
    return d;
}
__device__ __forceinline__ uint32_t hadd2_u(uint32_t a, uint32_t b) {
    uint32_t d;
    asm("add.rn.f16x2 %0, %1, %2;" : "=r"(d) : "r"(a), "r"(b));
    return d;
}

// 128 threads: 2 lanes per grid point (p = tid>>1, s = tid&1); lane s owns
// one full 16-unit layer as 8 f32x2 pairs.
//
// PACKED HALF TANH: per pair, f32x2 z -> one cvt.rn.f16x2.f32 -> one
// tanh.approx.f16x2 (MUFU) -> HFMA2 accumulate with wc in half2.
// MUFU instructions per lane drop 16 -> 8, so the per-SMSP MUFU drain
// halves (128 -> 64 cyc) — the dominant per-step term after R11.
// gamma*DT is applied ONCE in f32 after the half accumulation (gdt*wc
// would be denormal in half). z stays f32 (folded stencil weights ~2300
// rely on f32 cancellation).
//
// SHFL-FREE REDUCE (R11): un = base + P0 + P1; producer lane stores its raw
// partial into a per-point float4 triplet {base, P0, P1} and goes straight
// to the barrier; consumers LDS.128 each neighbor triplet and reconstruct
// u = (base+P0)+P1 — identical op order in every lane.
//
// Boundary (p=0,63): Ch=0 and base=0 => un == 0, no select on store path.
// Stencil folded into weights (f64 at init): z = Wuc*uc + Wp*up + Wm*um + B,
//   Wp = 31.5*Wg + 3969*Wl, Wm = -31.5*Wg + 3969*Wl, Wuc = Wu - 7938*Wl.
__global__ __launch_bounds__(128, 1) void scct_kernel(
    const float* __restrict__ u0,  const float* __restrict__ w1,
    const float* __restrict__ b1,  const float* __restrict__ w2,
    const float* __restrict__ b2,  const float* __restrict__ wc,
    const float* __restrict__ bc,  const float* __restrict__ gamma_p,
    const int*   __restrict__ nt_p, float* __restrict__ out)
{
    __shared__ float4 ub4[2][NXX];   // {base, P0, P1, unused} per point

    const int tid = threadIdx.x;
    const int p = tid >> 1;   // grid point 0..63
    const int s = tid & 1;    // layer select

    const float* wsel = s ? w2 : w1;
    const float* bsel = s ? b2 : b1;

    const float gmm = *gamma_p;
    const float gdt = gmm * DTT;
    const bool interior = (p > 0) && (p < NXX - 1);

    uint64_t Wp2[8], Wm2[8], Wuc2[8], Bq2[8];
    uint32_t Ch2[8];                 // wc pairs in half2 (UNscaled)
#pragma unroll
    for (int j = 0; j < 8; j++) {
        float pl[2], ml[2], ul[2], bl[2], cl[2];
#pragma unroll
        for (int h = 0; h < 2; h++) {
            int q = 2 * j + h;
            double Wu = (double)wsel[q * 3 + 0];
            double Wg = (double)wsel[q * 3 + 1];
            double Wl = (double)wsel[q * 3 + 2];
            if (interior) {
                pl[h] = (float)( 31.5 * Wg + 3969.0 * Wl);
                ml[h] = (float)(-31.5 * Wg + 3969.0 * Wl);
                ul[h] = (float)(Wu - 7938.0 * Wl);
                cl[h] = wc[s * 16 + q];
            } else {
                pl[h] = 0.0f;
                ml[h] = 0.0f;
                ul[h] = (float)Wu;
                cl[h] = 0.0f;             // boundary: P contributions vanish
            }
            bl[h] = bsel[q];
        }
        Wp2[j]  = pack2(pl[0], pl[1]);
        Wm2[j]  = pack2(ml[0], ml[1]);
        Wuc2[j] = pack2(ul[0], ul[1]);
        Bq2[j]  = pack2(bl[0], bl[1]);
        Ch2[j]  = cvt_h2(cl[0], cl[1]);   // h0 = unit q0, h1 = unit q1
    }
    const float Kc = gdt * (*bc);
    const int Nt = *nt_p;

    if (tid < NXX) {
        float v = u0[tid];
        ub4[0][tid] = make_float4(v, 0.0f, 0.0f, 0.0f);  // triplet form of u0
    }
    __syncthreads();

    const float INVDX2 = 3969.0f;  // 63^2

    const int pm = (p == 0) ? 0 : p - 1;
    const int pp = (p == NXX - 1) ? NXX - 1 : p + 1;

    int cur = 0;

    for (int it = 0; it < Nt; ++it) {
        // ---- chain head: 3 pipelined LDS.128 (neighbors + own point) ----
        const float4 m4 = ub4[cur][pm];
        const float4 p4 = ub4[cur][pp];
        const float4 c4 = ub4[cur][p];

        // reconstruct u values (identical op order in every lane)
        const float um = (m4.x + m4.y) + m4.z;
        const float up = (p4.x + p4.y) + p4.z;
        const float uc = (c4.x + c4.y) + c4.z;

        const uint64_t um2 = pack2(um, um);
        const uint64_t up2 = pack2(up, up);
        const uint64_t uc2 = pack2(uc, uc);

        // ---- MLP: 8 pairs; f32 z -> half2 -> packed tanh -> HFMA2 acc ----
        uint32_t A0 = 0u, A1 = 0u;     // half2 accumulators (zero = +0,+0)
#pragma unroll
        for (int j = 0; j < 8; j++) {
            uint64_t z2 = fma2(Wuc2[j], uc2,
                          fma2(Wp2[j], up2,
                          fma2(Wm2[j], um2, Bq2[j])));
            float zl, zh;
            unpack2(z2, zl, zh);
            uint32_t t2 = tanh_h2(cvt_h2(zl, zh));
            if (j & 1) A1 = hfma2_u(Ch2[j], t2, A1);
            else       A0 = hfma2_u(Ch2[j], t2, A0);
        }
        // half2 -> f32, apply gamma*DT once
        const uint32_t Sh = hadd2_u(A0, A1);
        const __half2 Shh = *reinterpret_cast<const __half2*>(&Sh);
        const float2 Sf = __half22float2(Shh);
        const float Ppart = gdt * (Sf.x + Sf.y);   // this lane's partial

        // base (both lanes; overlaps the MUFU stream)
        const float lx   = ((up - 2.0f * uc) + um) * INVDX2;
        const float cb   = fmaf(0.5f, uc, -(uc * uc * uc));
        const float core = fmaf(0.8f, lx, cb);
        const float base = interior ? (fmaf(DTT, core, uc) + Kc) : 0.0f;

        // ---- store raw triplet, NO reduce before the barrier ----
        float4* dst = &ub4[cur ^ 1][p];
        if (s == 0) {
            *reinterpret_cast<float2*>(dst) = make_float2(base, Ppart); // .xy
        } else {
            dst->z = Ppart;                                             // .z
        }
        __syncthreads();

        cur ^= 1;
    }

    // ---- epilogue: reconstruct u, then phi2 + histogram entropy ----
    __shared__ float uf[NXX];
    if (tid < NXX) {
        float4 v = ub4[cur][tid];
        float u = (v.x + v.y) + v.z;
        uf[tid] = u;
        out[tid] = u;
    }
    __syncthreads();

    if (tid == 0) {
        float s2 = 0.0f, vmax = 0.0f;
        for (int i = 0; i < NXX; i++) {
            float u = uf[i];
            s2 += u * u;
            vmax = fmaxf(vmax, fabsf(u));
        }
        float phi2 = s2 * (1.0f / 64.0f);

        int hist[64];
#pragma unroll
        for (int i = 0; i < 64; i++) hist[i] = 0;
        float denom = fmaxf(vmax, 1e-12f);
        for (int i = 0; i < NXX; i++) {
            float vn = fabsf(uf[i]) / denom;   // IEEE div, matches ref
            int b = (int)(vn * 64.0f);
            if (b > 63) b = 63;
            hist[b]++;
        }
        float H = 0.0f;
        for (int i = 0; i < 64; i++) {
            if (hist[i] > 0) {
                float pb = (float)hist[i] * (1.0f / 64.0f);
                H -= pb * logf(pb);
            }
        }
        if (vmax < 1e-12f) H = 0.0f;
        out[64] = phi2;
        out[65] = H;
    }
}

extern "C" void kernel_launch(void* const* d_in, const int* in_sizes, int n_in,
                              void* d_out, int out_size) {
    (void)in_sizes; (void)n_in; (void)out_size;
    scct_kernel<<<1, 128>>>(
        (const float*)d_in[0],  // u0
        (const float*)d_in[1],  // w1
        (const float*)d_in[2],  // b1
        (const float*)d_in[3],  // w2
        (const float*)d_in[4],  // b2
        (const float*)d_in[5],  // wc
        (const float*)d_in[6],  // bc
        (const float*)d_in[7],  // gamma
        (const int*)  d_in[8],  // Nt
        (float*)d_out);
}

// round 15
// speedup vs baseline: 1.1590x; 1.1590x over previous
#include <cuda_runtime.h>
#include <cstdint>

#define NXX 64
#define DTT 1e-4f

__device__ __forceinline__ float tanh_approx(float x) {
    float t;
    asm("tanh.approx.f32 %0, %1;" : "=f"(t) : "f"(x));
    return t;
}
__device__ __forceinline__ uint64_t pack2(float lo, float hi) {
    uint64_t r;
    asm("mov.b64 %0, {%1, %2};" : "=l"(r) : "f"(lo), "f"(hi));
    return r;
}
__device__ __forceinline__ void unpack2(uint64_t v, float& lo, float& hi) {
    asm("mov.b64 {%0, %1}, %2;" : "=f"(lo), "=f"(hi) : "l"(v));
}
__device__ __forceinline__ uint64_t fma2(uint64_t a, uint64_t b, uint64_t c) {
    uint64_t d;
    asm("fma.rn.f32x2 %0, %1, %2, %3;" : "=l"(d) : "l"(a), "l"(b), "l"(c));
    return d;
}
__device__ __forceinline__ uint64_t add2(uint64_t a, uint64_t b) {
    uint64_t d;
    asm("add.rn.f32x2 %0, %1, %2;" : "=l"(d) : "l"(a), "l"(b));
    return d;
}

// 128 threads: 2 lanes per grid point (p = tid>>1, s = tid&1); lane s owns
// one full 16-unit layer as 8 f32x2 pairs (scalar f32 tanh on MUFU — the
// f16x2 tanh experiment regressed and is reverted).
//
// uc WITHOUT SMEM: after the per-lane reduce, Poth = shfl_xor(Ppart,1) is
// issued BEFORE __syncthreads — its latency drains under the STS+barrier.
// Post-barrier, every lane reconstructs un = (base+P0)+P1 from registers,
// so zb = Wuc*uc + B (8 fma2) runs inside the neighbor-LDS window instead
// of waiting on shared memory.
//
// PAIR EXCHANGE: producer stores {a = base+P0, b = P1} (one STS.32 per
// lane); consumers reconstruct neighbor u = a+b (one add, depth 4).
// Producer's un uses the identical value and op order, so all lanes agree
// bitwise.
//
// Boundary (p=0,63): Cq=0 and base=0 => un == 0.
// Stencil folded into weights (f64 at init): z = Wuc*uc + Wp*up + Wm*um + B,
//   Wp = 31.5*Wg + 3969*Wl, Wm = -31.5*Wg + 3969*Wl, Wuc = Wu - 7938*Wl.
// Head folded: Cq = gamma*DT*wc, Kc = gamma*DT*bc.
__global__ __launch_bounds__(128, 1) void scct_kernel(
    const float* __restrict__ u0,  const float* __restrict__ w1,
    const float* __restrict__ b1,  const float* __restrict__ w2,
    const float* __restrict__ b2,  const float* __restrict__ wc,
    const float* __restrict__ bc,  const float* __restrict__ gamma_p,
    const int*   __restrict__ nt_p, float* __restrict__ out)
{
    __shared__ float2 ab[2][NXX];    // {a = base+P0, b = P1} per point

    const int tid = threadIdx.x;
    const int p = tid >> 1;   // grid point 0..63
    const int s = tid & 1;    // layer select

    const float* wsel = s ? w2 : w1;
    const float* bsel = s ? b2 : b1;

    const float gmm = *gamma_p;
    const float gdt = gmm * DTT;
    const bool interior = (p > 0) && (p < NXX - 1);

    uint64_t Wp2[8], Wm2[8], Wuc2[8], Bq2[8], Cq2[8];
#pragma unroll
    for (int j = 0; j < 8; j++) {
        float pl[2], ml[2], ul[2], bl[2], cl[2];
#pragma unroll
        for (int h = 0; h < 2; h++) {
            int q = 2 * j + h;
            double Wu = (double)wsel[q * 3 + 0];
            double Wg = (double)wsel[q * 3 + 1];
            double Wl = (double)wsel[q * 3 + 2];
            if (interior) {
                pl[h] = (float)( 31.5 * Wg + 3969.0 * Wl);
                ml[h] = (float)(-31.5 * Wg + 3969.0 * Wl);
                ul[h] = (float)(Wu - 7938.0 * Wl);
                cl[h] = gdt * wc[s * 16 + q];
            } else {
                pl[h] = 0.0f;
                ml[h] = 0.0f;
                ul[h] = (float)Wu;
                cl[h] = 0.0f;             // boundary: P contributions vanish
            }
            bl[h] = bsel[q];
        }
        Wp2[j]  = pack2(pl[0], pl[1]);
        Wm2[j]  = pack2(ml[0], ml[1]);
        Wuc2[j] = pack2(ul[0], ul[1]);
        Bq2[j]  = pack2(bl[0], bl[1]);
        Cq2[j]  = pack2(cl[0], cl[1]);
    }
    const float Kc = gdt * (*bc);
    const int Nt = *nt_p;

    if (tid < NXX) ab[0][tid] = make_float2(u0[tid], 0.0f);  // a=u0, b=0
    __syncthreads();

    const float INVDX2 = 3969.0f;  // 63^2

    const int pm = (p == 0) ? 0 : p - 1;
    const int pp = (p == NXX - 1) ? NXX - 1 : p + 1;

    // Register state: un(t) = (base + P0) + P1 with P0 = layer-1 partial.
    float base = u0[p];
    float Pown = 0.0f, Poth = 0.0f;
    int cur = 0;

#pragma unroll 2
    for (int it = 0; it < Nt; ++it) {
        // ---- chain head: 2 pipelined LDS.64 (neighbors only) ----
        const float2 mab = ab[cur][pm];
        const float2 pab = ab[cur][pp];

        // un from registers (shfl result arrived under the previous barrier)
        const float P0v = s ? Poth : Pown;
        const float P1v = s ? Pown : Poth;
        const float uc = (base + P0v) + P1v;   // == consumers' a+b bitwise
        const uint64_t uc2 = pack2(uc, uc);

        // zb + cb: register-only, fill the LDS latency window
        uint64_t zb2[8];
#pragma unroll
        for (int j = 0; j < 8; j++) zb2[j] = fma2(Wuc2[j], uc2, Bq2[j]);
        const float cb = fmaf(0.5f, uc, -(uc * uc * uc));   // 0.5u - u^3

        // neighbor u recon: ONE add each
        const float um = mab.x + mab.y;
        const float up = pab.x + pab.y;
        const uint64_t um2 = pack2(um, um);
        const uint64_t up2 = pack2(up, up);

        // ---- MLP: 8 f32x2 pairs, 2-fma2 z, 4 independent acc chains ----
        uint64_t A0 = 0ull, A1 = 0ull, A2 = 0ull, A3 = 0ull;
#pragma unroll
        for (int j = 0; j < 8; j++) {
            uint64_t z2 = fma2(Wp2[j], up2, fma2(Wm2[j], um2, zb2[j]));
            float zl, zh;
            unpack2(z2, zl, zh);
            uint64_t t2 = pack2(tanh_approx(zl), tanh_approx(zh));
            switch (j & 3) {
                case 0: A0 = fma2(Cq2[j], t2, A0); break;
                case 1: A1 = fma2(Cq2[j], t2, A1); break;
                case 2: A2 = fma2(Cq2[j], t2, A2); break;
                default: A3 = fma2(Cq2[j], t2, A3); break;
            }
        }
        float al, ah;
        unpack2(add2(add2(A0, A1), add2(A2, A3)), al, ah);
        const float Ppart = al + ah;          // this lane's partial head sum

        // base for next step (overlaps the MUFU drain)
        const float lx    = ((up - 2.0f * uc) + um) * INVDX2;
        const float core  = fmaf(0.8f, lx, cb);
        const float basen = interior ? (fmaf(DTT, core, uc) + Kc) : 0.0f;

        // ---- shfl first (latency drains under STS+barrier), then store ----
        Poth = __shfl_xor_sync(0xffffffffu, Ppart, 1);
        const float val = (s == 0) ? (basen + Ppart) : Ppart;
        reinterpret_cast<float*>(&ab[cur ^ 1][p])[s] = val;
        __syncthreads();

        Pown = Ppart;
        base = basen;
        cur ^= 1;
    }

    // ---- epilogue: reconstruct u, then phi2 + histogram entropy ----
    __shared__ float uf[NXX];
    if (tid < NXX) {
        float2 v = ab[cur][tid];
        float u = v.x + v.y;
        uf[tid] = u;
        out[tid] = u;
    }
    __syncthreads();

    if (tid == 0) {
        float s2 = 0.0f, vmax = 0.0f;
        for (int i = 0; i < NXX; i++) {
            float u = uf[i];
            s2 += u * u;
            vmax = fmaxf(vmax, fabsf(u));
        }
        float phi2 = s2 * (1.0f / 64.0f);

        int hist[64];
#pragma unroll
        for (int i = 0; i < 64; i++) hist[i] = 0;
        float denom = fmaxf(vmax, 1e-12f);
        for (int i = 0; i < NXX; i++) {
            float vn = fabsf(uf[i]) / denom;   // IEEE div, matches ref
            int b = (int)(vn * 64.0f);
            if (b > 63) b = 63;
            hist[b]++;
        }
        float H = 0.0f;
        for (int i = 0; i < 64; i++) {
            if (hist[i] > 0) {
                float pb = (float)hist[i] * (1.0f / 64.0f);
                H -= pb * logf(pb);
            }
        }
        if (vmax < 1e-12f) H = 0.0f;
        out[64] = phi2;
        out[65] = H;
    }
}

extern "C" void kernel_launch(void* const* d_in, const int* in_sizes, int n_in,
                              void* d_out, int out_size) {
    (void)in_sizes; (void)n_in; (void)out_size;
    scct_kernel<<<1, 128>>>(
        (const float*)d_in[0],  // u0
        (const float*)d_in[1],  // w1
        (const float*)d_in[2],  // b1
        (const float*)d_in[3],  // w2
        (const float*)d_in[4],  // b2
        (const float*)d_in[5],  // wc
        (const float*)d_in[6],  // bc
        (const float*)d_in[7],  // gamma
        (const int*)  d_in[8],  // Nt
        (float*)d_out);
}

// round 16
// speedup vs baseline: 1.2048x; 1.0395x over previous
#include <cuda_runtime.h>
#include <cstdint>

#define NXX 64
#define DTT 1e-4f

__device__ __forceinline__ float tanh_approx(float x) {
    float t;
    asm("tanh.approx.f32 %0, %1;" : "=f"(t) : "f"(x));
    return t;
}
__device__ __forceinline__ uint64_t pack2(float lo, float hi) {
    uint64_t r;
    asm("mov.b64 %0, {%1, %2};" : "=l"(r) : "f"(lo), "f"(hi));
    return r;
}
__device__ __forceinline__ void unpack2(uint64_t v, float& lo, float& hi) {
    asm("mov.b64 {%0, %1}, %2;" : "=f"(lo), "=f"(hi) : "l"(v));
}
__device__ __forceinline__ uint64_t fma2(uint64_t a, uint64_t b, uint64_t c) {
    uint64_t d;
    asm("fma.rn.f32x2 %0, %1, %2, %3;" : "=l"(d) : "l"(a), "l"(b), "l"(c));
    return d;
}

// 128 threads: 2 lanes per grid point (p = tid>>1, s = tid&1); lane s owns
// one full 16-unit layer as 8 f32x2 pairs (scalar f32 tanh on MUFU).
//
// PROGRESSIVE SUM: S = fma2(Cq_j, t_j, S) chained as tanh results arrive
// (fma lat 4 << 16-cyc tanh spacing), with basen FOLDED INTO S's init
// ({s==0 ? basen : 0, 0}). After the last tanh the tail is just
// fma2 -> unpack -> add -> shfl/STS: the add2 tree and the base select-add
// are gone from the pre-barrier critical path.
//
// PAIR EXCHANGE (R15): producer stores val (lane 0: basen+P0, lane 1: P1);
// consumers reconstruct u = a+b. In-lane: uc = val + shfl_xor(val,1) —
// commutative add, bitwise identical to consumers' a+b. The shfl is issued
// pre-barrier and drains under STS+bar.
//
// Boundary (p=0,63): Cq=0 and basen=0 => un == 0.
// Stencil folded into weights (f64 at init): z = Wuc*uc + Wp*up + Wm*um + B,
//   Wp = 31.5*Wg + 3969*Wl, Wm = -31.5*Wg + 3969*Wl, Wuc = Wu - 7938*Wl.
// Head folded: Cq = gamma*DT*wc, Kc = gamma*DT*bc.
__global__ __launch_bounds__(128, 1) void scct_kernel(
    const float* __restrict__ u0,  const float* __restrict__ w1,
    const float* __restrict__ b1,  const float* __restrict__ w2,
    const float* __restrict__ b2,  const float* __restrict__ wc,
    const float* __restrict__ bc,  const float* __restrict__ gamma_p,
    const int*   __restrict__ nt_p, float* __restrict__ out)
{
    __shared__ float2 ab[2][NXX];    // {lane0 val, lane1 val} per point

    const int tid = threadIdx.x;
    const int p = tid >> 1;   // grid point 0..63
    const int s = tid & 1;    // layer select

    const float* wsel = s ? w2 : w1;
    const float* bsel = s ? b2 : b1;

    const float gmm = *gamma_p;
    const float gdt = gmm * DTT;
    const bool interior = (p > 0) && (p < NXX - 1);

    uint64_t Wp2[8], Wm2[8], Wuc2[8], Bq2[8], Cq2[8];
#pragma unroll
    for (int j = 0; j < 8; j++) {
        float pl[2], ml[2], ul[2], bl[2], cl[2];
#pragma unroll
        for (int h = 0; h < 2; h++) {
            int q = 2 * j + h;
            double Wu = (double)wsel[q * 3 + 0];
            double Wg = (double)wsel[q * 3 + 1];
            double Wl = (double)wsel[q * 3 + 2];
            if (interior) {
                pl[h] = (float)( 31.5 * Wg + 3969.0 * Wl);
                ml[h] = (float)(-31.5 * Wg + 3969.0 * Wl);
                ul[h] = (float)(Wu - 7938.0 * Wl);
                cl[h] = gdt * wc[s * 16 + q];
            } else {
                pl[h] = 0.0f;
                ml[h] = 0.0f;
                ul[h] = (float)Wu;
                cl[h] = 0.0f;             // boundary: P contributions vanish
            }
            bl[h] = bsel[q];
        }
        Wp2[j]  = pack2(pl[0], pl[1]);
        Wm2[j]  = pack2(ml[0], ml[1]);
        Wuc2[j] = pack2(ul[0], ul[1]);
        Bq2[j]  = pack2(bl[0], bl[1]);
        Cq2[j]  = pack2(cl[0], cl[1]);
    }
    const float Kc = gdt * (*bc);
    const int Nt = *nt_p;

    if (tid < NXX) ab[0][tid] = make_float2(u0[tid], 0.0f);  // a=u0, b=0
    __syncthreads();

    const float INVDX2 = 3969.0f;  // 63^2

    const int pm = (p == 0) ? 0 : p - 1;
    const int pp = (p == NXX - 1) ? NXX - 1 : p + 1;

    // Register state: u(t) = val + Poth (val = this lane's stored value).
    float val  = u0[p];   // lane 0 slot carries u0; lane 1 slot is 0
    float Poth = 0.0f;
    if (s == 1) { val = 0.0f; Poth = u0[p]; }
    int cur = 0;

#pragma unroll 2
    for (int it = 0; it < Nt; ++it) {
        // ---- chain head: 2 pipelined LDS.64 (neighbors only) ----
        const float2 mab = ab[cur][pm];
        const float2 pab = ab[cur][pp];

        // uc from registers (shfl result arrived under the previous barrier)
        const float uc = val + Poth;           // == consumers' a+b bitwise
        const uint64_t uc2 = pack2(uc, uc);

        // zb + cb: register-only, fill the LDS latency window
        uint64_t zb2[8];
#pragma unroll
        for (int j = 0; j < 8; j++) zb2[j] = fma2(Wuc2[j], uc2, Bq2[j]);
        const float cb = fmaf(0.5f, uc, -(uc * uc * uc));   // 0.5u - u^3

        // neighbor u recon: ONE add each
        const float um = mab.x + mab.y;
        const float up = pab.x + pab.y;
        const uint64_t um2 = pack2(um, um);
        const uint64_t up2 = pack2(up, up);

        // basen early (hidden under the MUFU drain)
        const float lx    = ((up - 2.0f * uc) + um) * INVDX2;
        const float core  = fmaf(0.8f, lx, cb);
        const float basen = interior ? (fmaf(DTT, core, uc) + Kc) : 0.0f;

        // ---- MLP: 8 f32x2 pairs, progressive sum seeded with basen ----
        uint64_t S = pack2((s == 0) ? basen : 0.0f, 0.0f);
#pragma unroll
        for (int j = 0; j < 8; j++) {
            uint64_t z2 = fma2(Wp2[j], up2, fma2(Wm2[j], um2, zb2[j]));
            float zl, zh;
            unpack2(z2, zl, zh);
            uint64_t t2 = pack2(tanh_approx(zl), tanh_approx(zh));
            S = fma2(Cq2[j], t2, S);
        }
        float Sl, Sh;
        unpack2(S, Sl, Sh);
        const float v = Sl + Sh;   // lane 0: basen+P0, lane 1: P1

        // ---- shfl first (latency drains under STS+barrier), then store ----
        const float oth = __shfl_xor_sync(0xffffffffu, v, 1);
        reinterpret_cast<float*>(&ab[cur ^ 1][p])[s] = v;
        __syncthreads();

        val = v;
        Poth = oth;
        cur ^= 1;
    }

    // ---- epilogue: reconstruct u, then phi2 + histogram entropy ----
    __shared__ float uf[NXX];
    if (tid < NXX) {
        float2 v2 = ab[cur][tid];
        float u = v2.x + v2.y;
        uf[tid] = u;
        out[tid] = u;
    }
    __syncthreads();

    if (tid == 0) {
        float s2 = 0.0f, vmax = 0.0f;
        for (int i = 0; i < NXX; i++) {
            float u = uf[i];
            s2 += u * u;
            vmax = fmaxf(vmax, fabsf(u));
        }
        float phi2 = s2 * (1.0f / 64.0f);

        int hist[64];
#pragma unroll
        for (int i = 0; i < 64; i++) hist[i] = 0;
        float denom = fmaxf(vmax, 1e-12f);
        for (int i = 0; i < NXX; i++) {
            float vn = fabsf(uf[i]) / denom;   // IEEE div, matches ref
            int b = (int)(vn * 64.0f);
            if (b > 63) b = 63;
            hist[b]++;
        }
        float H = 0.0f;
        for (int i = 0; i < 64; i++) {
            if (hist[i] > 0) {
                float pb = (float)hist[i] * (1.0f / 64.0f);
                H -= pb * logf(pb);
            }
        }
        if (vmax < 1e-12f) H = 0.0f;
        out[64] = phi2;
        out[65] = H;
    }
}

extern "C" void kernel_launch(void* const* d_in, const int* in_sizes, int n_in,
                              void* d_out, int out_size) {
    (void)in_sizes; (void)n_in; (void)out_size;
    scct_kernel<<<1, 128>>>(
        (const float*)d_in[0],  // u0
        (const float*)d_in[1],  // w1
        (const float*)d_in[2],  // b1
        (const float*)d_in[3],  // w2
        (const float*)d_in[4],  // b2
        (const float*)d_in[5],  // wc
        (const float*)d_in[6],  // bc
        (const float*)d_in[7],  // gamma
        (const int*)  d_in[8],  // Nt
        (float*)d_out);
}